// round 9
// baseline (speedup 1.0000x reference)
#include <cuda_runtime.h>

#define NROWS 8192
#define DDIM  8192
#define KIN   1024
#define NT    64
#define GRID  2048
#define RPB   (NROWS / GRID)   // 4 rows per block

typedef unsigned long long ull;

// ---- packed f32x2 helpers (Blackwell sm_103a) ----
__device__ __forceinline__ ull pack2(float lo, float hi) {
    ull r; asm("mov.b64 %0, {%1, %2};" : "=l"(r) : "f"(lo), "f"(hi)); return r;
}
__device__ __forceinline__ void unpack2(ull v, float& lo, float& hi) {
    asm("mov.b64 {%0, %1}, %2;" : "=f"(lo), "=f"(hi) : "l"(v));
}
__device__ __forceinline__ ull f2add(ull a, ull b) {
    ull r; asm("add.rn.f32x2 %0, %1, %2;" : "=l"(r) : "l"(a), "l"(b)); return r;
}
// a - b == fma(b, -1, a)
__device__ __forceinline__ ull f2sub(ull a, ull b) {
    const ull NEG1 = 0xBF800000BF800000ULL;
    ull r; asm("fma.rn.f32x2 %0, %1, %2, %3;" : "=l"(r) : "l"(b), "l"(NEG1), "l"(a)); return r;
}
__device__ __forceinline__ ull f2mul(ull a, ull b) {
    ull r; asm("mul.rn.f32x2 %0, %1, %2;" : "=l"(r) : "l"(a), "l"(b)); return r;
}

// Storage swizzle: slot(e) = e ^ (((e>>7)&31)<<2)  (perturbs bits 2..6 only)
__device__ __forceinline__ int slot(int e) {
    return e ^ (((e >> 7) & 31) << 2);
}

__global__ void __launch_bounds__(NT, 6) fwht_kernel(
    const float* __restrict__ u, const int* __restrict__ idx, float* __restrict__ out)
{
    __shared__ float sm[DDIM];   // 32 KB, single in-place buffer
    float4* smv = reinterpret_cast<float4*>(sm);

    const int t = threadIdx.x;   // 0..63

    // ---- row-invariant: 16 sorted keys per thread ----
    int id[16];
    {
        const int4* idx4 = reinterpret_cast<const int4*>(idx);
#pragma unroll
        for (int i = 0; i < 4; i++) {
            int4 v = idx4[4 * t + i];
            id[4*i] = v.x; id[4*i+1] = v.y; id[4*i+2] = v.z; id[4*i+3] = v.w;
        }
    }
    const int prev0 = (t == 0) ? -1 : idx[16 * t - 1];

    // P1 addressing constants
    const int tm = t & 31;
    const int qb = t << 5;

    int row = blockIdx.x;
    // first row's u (16 values per thread)
    float4 uv[4];
    {
        const float4* u4 = reinterpret_cast<const float4*>(u + (long)row * KIN);
#pragma unroll
        for (int i = 0; i < 4; i++) uv[i] = u4[4 * t + i];
    }

#pragma unroll 1
    for (int it = 0; it < RPB; it++) {
        const float* urow = u + (long)row * KIN;

        // ---- zero smem (32KB, STS.128, conflict-free) ----
        const float4 z4 = make_float4(0.f, 0.f, 0.f, 0.f);
#pragma unroll
        for (int i = 0; i < DDIM / 4 / NT; i++) smv[t + NT * i] = z4;
        __syncthreads();

        // ---- scatter: idx SORTED -> run-leader plain stores (no atomics) ----
        {
            float uu[16];
#pragma unroll
            for (int i = 0; i < 4; i++) {
                uu[4*i] = uv[i].x; uu[4*i+1] = uv[i].y; uu[4*i+2] = uv[i].z; uu[4*i+3] = uv[i].w;
            }
            int prev = prev0;
#pragma unroll
            for (int p = 0; p < 16; p++) {
                if (id[p] != prev) {
                    float val = uu[p];
                    int q = p + 1;
                    while (q < 16 && id[q] == id[p]) { val += uu[q]; q++; }
                    if (q == 16) {
                        int j = 16 * t + 16;   // run spills past this thread's keys (rare)
                        while (j < KIN && idx[j] == id[p]) { val += urow[j]; j++; }
                    }
                    sm[slot(id[p])] = val;
                }
                prev = id[p];
            }
        }
        __syncthreads();

        // ==== Phase 1: thread owns e in [128t, 128t+128); bits 0..6 in registers ====
        // e-quad c stored at slot-quad 32t + (c ^ (t&31))  -> 32x LDS.128 conflict-free
        {
            ull y[64];
#pragma unroll
            for (int c = 0; c < 32; c++) {
                float4 q = smv[qb + (c ^ tm)];
                y[2 * c]     = pack2(q.x + q.y, q.x - q.y);   // fold bit 0
                y[2 * c + 1] = pack2(q.z + q.w, q.z - q.w);
            }
            // bits 1..6: 6 packed stages
#pragma unroll
            for (int m = 32; m >= 1; m >>= 1) {
#pragma unroll
                for (int j = 0; j < 64; j++) {
                    if (!(j & m)) {
                        ull a = y[j], b = y[j | m];
                        y[j]     = f2add(a, b);
                        y[j | m] = f2sub(a, b);
                    }
                }
            }
            // write back IN-PLACE (thread-exclusive slots)
#pragma unroll
            for (int c = 0; c < 32; c++) {
                float a0, a1, b0, b1;
                unpack2(y[2 * c], a0, a1);
                unpack2(y[2 * c + 1], b0, b1);
                smv[qb + (c ^ tm)] = make_float4(a0, a1, b0, b1);
            }
        }
        __syncthreads();   // P2 reads cross-thread

        // ---- prefetch next row's u (hidden under Phase 2; y[] is dead here) ----
        if (it + 1 < RPB) {
            const float4* u4n = reinterpret_cast<const float4*>(u + (long)(row + GRID) * KIN);
#pragma unroll
            for (int i = 0; i < 4; i++) uv[i] = u4n[4 * t + i];
        }

        // ==== Phase 2: bits 7..12; each thread handles tau = t and t+64 ====
        const float SCALE = 0.011048543456039806f;  // 1/sqrt(8192)
        const ull SC2 = pack2(SCALE, SCALE);
        float* orow = out + (long)row * DDIM;
#pragma unroll 1
        for (int pass = 0; pass < 2; pass++) {
            const int tau = t + 64 * pass;
            ull z[32];
            // read e = tau + 128m at slot = 128m + (tau ^ ((m&31)<<2)); fold bit 7
#pragma unroll
            for (int h = 0; h < 32; h++) {
                const int m0 = 2 * h, m1 = 2 * h + 1;
                float a = sm[128 * m0 + (tau ^ ((m0 & 31) << 2))];
                float b = sm[128 * m1 + (tau ^ ((m1 & 31) << 2))];
                z[h] = pack2(a + b, a - b);
            }
            // bits 8..12: 5 packed stages
#pragma unroll
            for (int m = 16; m >= 1; m >>= 1) {
#pragma unroll
                for (int j = 0; j < 32; j++) {
                    if (!(j & m)) {
                        ull a = z[j], b = z[j | m];
                        z[j]     = f2add(a, b);
                        z[j | m] = f2sub(a, b);
                    }
                }
            }
            // scale + store (coalesced: lanes contiguous)
#pragma unroll
            for (int h = 0; h < 32; h++) {
                float lo, hi;
                unpack2(f2mul(z[h], SC2), lo, hi);
                orow[tau + 256 * h]       = lo;
                orow[tau + 256 * h + 128] = hi;
            }
        }
        __syncthreads();   // all P2 reads done before next row's zero overwrites

        row += GRID;
    }
}

extern "C" void kernel_launch(void* const* d_in, const int* in_sizes, int n_in,
                              void* d_out, int out_size)
{
    const float* u   = (const float*)d_in[0];
    const int*   idx = (const int*)d_in[1];
    float*       out = (float*)d_out;
    fwht_kernel<<<GRID, NT>>>(u, idx, out);
}

// round 10
// speedup vs baseline: 1.1328x; 1.1328x over previous
#include <cuda_runtime.h>

#define NROWS 8192
#define DDIM  8192
#define KIN   1024
#define NT    64

typedef unsigned long long ull;

// ---- packed f32x2 helpers (Blackwell sm_103a) ----
__device__ __forceinline__ ull pack2(float lo, float hi) {
    ull r; asm("mov.b64 %0, {%1, %2};" : "=l"(r) : "f"(lo), "f"(hi)); return r;
}
__device__ __forceinline__ void unpack2(ull v, float& lo, float& hi) {
    asm("mov.b64 {%0, %1}, %2;" : "=f"(lo), "=f"(hi) : "l"(v));
}
__device__ __forceinline__ ull f2add(ull a, ull b) {
    ull r; asm("add.rn.f32x2 %0, %1, %2;" : "=l"(r) : "l"(a), "l"(b)); return r;
}
// a - b == fma(b, -1, a)
__device__ __forceinline__ ull f2sub(ull a, ull b) {
    const ull NEG1 = 0xBF800000BF800000ULL;
    ull r; asm("fma.rn.f32x2 %0, %1, %2, %3;" : "=l"(r) : "l"(b), "l"(NEG1), "l"(a)); return r;
}
__device__ __forceinline__ ull f2mul(ull a, ull b) {
    ull r; asm("mul.rn.f32x2 %0, %1, %2;" : "=l"(r) : "l"(a), "l"(b)); return r;
}

// Storage swizzle: slot(e) = e ^ (((e>>7)&31)<<2)  (perturbs bits 2..6 only)
__device__ __forceinline__ int slot(int e) {
    return e ^ (((e >> 7) & 31) << 2);
}

__global__ void __launch_bounds__(NT, 6) fwht_kernel(
    const float* __restrict__ u, const int* __restrict__ idx, float* __restrict__ out)
{
    __shared__ float sm[DDIM];   // 32 KB, single in-place buffer
    float4* smv = reinterpret_cast<float4*>(sm);

    const int t   = threadIdx.x;       // 0..63
    const int row = blockIdx.x;
    const float* urow = u + (long)row * KIN;

    // ---- early global loads (16 keys + 16 values per thread) ----
    int   id[16];
    float uu[16];
    {
        const int4*   idx4 = reinterpret_cast<const int4*>(idx);
        const float4* u4   = reinterpret_cast<const float4*>(urow);
#pragma unroll
        for (int i = 0; i < 4; i++) {
            int4   v = idx4[4 * t + i];
            float4 w = u4[4 * t + i];
            id[4*i] = v.x; id[4*i+1] = v.y; id[4*i+2] = v.z; id[4*i+3] = v.w;
            uu[4*i] = w.x; uu[4*i+1] = w.y; uu[4*i+2] = w.z; uu[4*i+3] = w.w;
        }
    }
    int prev = (t == 0) ? -1 : idx[16 * t - 1];

    // ---- zero smem (32KB, STS.128, conflict-free), overlaps LDG latency ----
    const float4 z4 = make_float4(0.f, 0.f, 0.f, 0.f);
#pragma unroll
    for (int i = 0; i < DDIM / 4 / NT; i++) smv[t + NT * i] = z4;
    __syncthreads();

    // ---- scatter, branch-free: leaders plain-store own value; duplicates atomicAdd ----
    unsigned lmask = 0;
#pragma unroll
    for (int p = 0; p < 16; p++) {
        bool lead = (id[p] != prev);
        if (lead) { lmask |= (1u << p); sm[slot(id[p])] = uu[p]; }
        prev = id[p];
    }
    __syncthreads();   // all leader stores complete before duplicate adds
#pragma unroll
    for (int p = 0; p < 16; p++) {
        if (!(lmask & (1u << p))) atomicAdd(&sm[slot(id[p])], uu[p]);
    }
    __syncthreads();

    // ==== Phase 1: thread owns e in [128t, 128t+128); bits 0..6 in registers ====
    // e-quad c stored at slot-quad 32t + (c ^ (t&31))  -> 32x LDS.128 conflict-free
    {
        ull y[64];
        const int tm = t & 31;
        const int qb = t << 5;
#pragma unroll
        for (int c = 0; c < 32; c++) {
            float4 q = smv[qb + (c ^ tm)];
            y[2 * c]     = pack2(q.x + q.y, q.x - q.y);   // fold bit 0
            y[2 * c + 1] = pack2(q.z + q.w, q.z - q.w);
        }
        // bits 1..6: 6 packed stages over pair-index p = 0..63
#pragma unroll
        for (int m = 32; m >= 1; m >>= 1) {
#pragma unroll
            for (int j = 0; j < 64; j++) {
                if (!(j & m)) {
                    ull a = y[j], b = y[j | m];
                    y[j]     = f2add(a, b);
                    y[j | m] = f2sub(a, b);
                }
            }
        }
        // write back IN-PLACE (thread-exclusive slots, same addresses)
#pragma unroll
        for (int c = 0; c < 32; c++) {
            float a0, a1, b0, b1;
            unpack2(y[2 * c], a0, a1);
            unpack2(y[2 * c + 1], b0, b1);
            smv[qb + (c ^ tm)] = make_float4(a0, a1, b0, b1);
        }
    }
    __syncthreads();   // P2 reads cross-thread

    // ==== Phase 2: bits 7..12; thread handles tau pair (2t, 2t+1), single pass ====
    // read e = tau + 128m at slot = 128m + (tau ^ ((m&31)<<2)); tau pair adjacent -> LDS.64
    {
        ull z[64];
        const int t2 = 2 * t;
#pragma unroll
        for (int m = 0; m < 64; m++) {
            float2 v = *reinterpret_cast<const float2*>(
                &sm[128 * m + (t2 ^ ((m & 31) << 2))]);
            z[m] = pack2(v.x, v.y);   // packed lanes = (tau0, tau1)
        }
        // 6 packed stages over m (bits 7..12)
#pragma unroll
        for (int mm = 32; mm >= 1; mm >>= 1) {
#pragma unroll
            for (int j = 0; j < 64; j++) {
                if (!(j & mm)) {
                    ull a = z[j], b = z[j | mm];
                    z[j]      = f2add(a, b);
                    z[j | mm] = f2sub(a, b);
                }
            }
        }
        // scale + store: float2 at orow[128m + 2t]  -> STG.64, coalesced
        const float SCALE = 0.011048543456039806f;  // 1/sqrt(8192)
        const ull SC2 = pack2(SCALE, SCALE);
        float2* orow2 = reinterpret_cast<float2*>(out + (long)row * DDIM);
#pragma unroll
        for (int m = 0; m < 64; m++) {
            float lo, hi;
            unpack2(f2mul(z[m], SC2), lo, hi);
            orow2[64 * m + t] = make_float2(lo, hi);
        }
    }
}

extern "C" void kernel_launch(void* const* d_in, const int* in_sizes, int n_in,
                              void* d_out, int out_size)
{
    const float* u   = (const float*)d_in[0];
    const int*   idx = (const int*)d_in[1];
    float*       out = (float*)d_out;
    fwht_kernel<<<NROWS, NT>>>(u, idx, out);
}

// round 11
// speedup vs baseline: 1.1655x; 1.0288x over previous
#include <cuda_runtime.h>

#define NROWS 8192
#define DDIM  8192
#define KIN   1024
#define NT    64

typedef unsigned long long ull;

// ---- packed f32x2 helpers (Blackwell sm_103a) ----
__device__ __forceinline__ ull pack2(float lo, float hi) {
    ull r; asm("mov.b64 %0, {%1, %2};" : "=l"(r) : "f"(lo), "f"(hi)); return r;
}
__device__ __forceinline__ void unpack2(ull v, float& lo, float& hi) {
    asm("mov.b64 {%0, %1}, %2;" : "=f"(lo), "=f"(hi) : "l"(v));
}
__device__ __forceinline__ ull f2add(ull a, ull b) {
    ull r; asm("add.rn.f32x2 %0, %1, %2;" : "=l"(r) : "l"(a), "l"(b)); return r;
}
// a - b == fma(b, -1, a)
__device__ __forceinline__ ull f2sub(ull a, ull b) {
    const ull NEG1 = 0xBF800000BF800000ULL;
    ull r; asm("fma.rn.f32x2 %0, %1, %2, %3;" : "=l"(r) : "l"(b), "l"(NEG1), "l"(a)); return r;
}
__device__ __forceinline__ ull f2mul(ull a, ull b) {
    ull r; asm("mul.rn.f32x2 %0, %1, %2;" : "=l"(r) : "l"(a), "l"(b)); return r;
}

// Storage swizzle: slot(e) = e ^ (((e>>7)&31)<<2)  (perturbs bits 2..6 only)
__device__ __forceinline__ int slot(int e) {
    return e ^ (((e >> 7) & 31) << 2);
}

__global__ void __launch_bounds__(NT, 6) fwht_kernel(
    const float* __restrict__ u, const int* __restrict__ idx, float* __restrict__ out)
{
    __shared__ float sm[DDIM];   // 32 KB, single in-place buffer
    float4* smv = reinterpret_cast<float4*>(sm);

    const int t   = threadIdx.x;       // 0..63
    const int row = blockIdx.x;
    const float* urow = u + (long)row * KIN;

    // ---- early global loads (16 keys + 16 values per thread) ----
    int4   iv[4];
    float4 uv[4];
    const int4*   idx4 = reinterpret_cast<const int4*>(idx);
    const float4* u4   = reinterpret_cast<const float4*>(urow);
#pragma unroll
    for (int i = 0; i < 4; i++) { iv[i] = idx4[4 * t + i]; uv[i] = u4[4 * t + i]; }
    int prev = (t == 0) ? -1 : idx[16 * t - 1];

    // ---- zero smem (32KB, STS.128, conflict-free), overlaps LDG latency ----
    const float4 z4 = make_float4(0.f, 0.f, 0.f, 0.f);
#pragma unroll
    for (int i = 0; i < DDIM / 4 / NT; i++) smv[t + NT * i] = z4;
    __syncthreads();

    // ---- scatter: idx SORTED -> run-leader plain stores (no atomics) ----
    {
        int   id[16]; float uu[16];
#pragma unroll
        for (int i = 0; i < 4; i++) {
            id[4*i] = iv[i].x; id[4*i+1] = iv[i].y; id[4*i+2] = iv[i].z; id[4*i+3] = iv[i].w;
            uu[4*i] = uv[i].x; uu[4*i+1] = uv[i].y; uu[4*i+2] = uv[i].z; uu[4*i+3] = uv[i].w;
        }
#pragma unroll
        for (int p = 0; p < 16; p++) {
            if (id[p] != prev) {
                float val = uu[p];
                int q = p + 1;
                while (q < 16 && id[q] == id[p]) { val += uu[q]; q++; }
                if (q == 16) {
                    int j = 16 * t + 16;   // run spills past this thread's keys (rare)
                    while (j < KIN && idx[j] == id[p]) { val += urow[j]; j++; }
                }
                sm[slot(id[p])] = val;
            }
            prev = id[p];
        }
    }
    __syncthreads();

    // ==== Phase 1: thread owns e in [128t, 128t+128); bits 0..6 in registers ====
    // e-quad c stored at slot-quad 32t + (c ^ (t&31))  -> 32x LDS.128 conflict-free
    {
        ull y[64];
        const int tm = t & 31;
        const int qb = t << 5;
#pragma unroll
        for (int c = 0; c < 32; c++) {
            float4 q = smv[qb + (c ^ tm)];
            y[2 * c]     = pack2(q.x + q.y, q.x - q.y);   // fold bit 0
            y[2 * c + 1] = pack2(q.z + q.w, q.z - q.w);
        }
        // bits 1..6: 6 packed stages over pair-index p = 0..63
#pragma unroll
        for (int m = 32; m >= 1; m >>= 1) {
#pragma unroll
            for (int j = 0; j < 64; j++) {
                if (!(j & m)) {
                    ull a = y[j], b = y[j | m];
                    y[j]     = f2add(a, b);
                    y[j | m] = f2sub(a, b);
                }
            }
        }
        // write back IN-PLACE (thread-exclusive slots, same addresses)
#pragma unroll
        for (int c = 0; c < 32; c++) {
            float a0, a1, b0, b1;
            unpack2(y[2 * c], a0, a1);
            unpack2(y[2 * c + 1], b0, b1);
            smv[qb + (c ^ tm)] = make_float4(a0, a1, b0, b1);
        }
    }
    __syncthreads();   // P2 reads cross-thread

    // ==== Phase 2: bits 7..12; thread handles tau pair (2t, 2t+1), single pass ====
    // read e = tau + 128m at slot = 128m + (tau ^ ((m&31)<<2)); tau pair adjacent -> LDS.64
    // (bank audit: addresses {2l^c} cover all 32 banks for any c -> conflict-free)
    {
        ull z[64];
        const int t2 = 2 * t;
#pragma unroll
        for (int m = 0; m < 64; m++) {
            float2 v = *reinterpret_cast<const float2*>(
                &sm[128 * m + (t2 ^ ((m & 31) << 2))]);
            z[m] = pack2(v.x, v.y);   // packed lanes = (tau0, tau1)
        }
        // 6 packed stages over m (bits 7..12)
#pragma unroll
        for (int mm = 32; mm >= 1; mm >>= 1) {
#pragma unroll
            for (int j = 0; j < 64; j++) {
                if (!(j & mm)) {
                    ull a = z[j], b = z[j | mm];
                    z[j]      = f2add(a, b);
                    z[j | mm] = f2sub(a, b);
                }
            }
        }
        // scale + store: float2 at orow[128m + 2t]  -> STG.64, coalesced
        const float SCALE = 0.011048543456039806f;  // 1/sqrt(8192)
        const ull SC2 = pack2(SCALE, SCALE);
        float2* orow2 = reinterpret_cast<float2*>(out + (long)row * DDIM);
#pragma unroll
        for (int m = 0; m < 64; m++) {
            float lo, hi;
            unpack2(f2mul(z[m], SC2), lo, hi);
            orow2[64 * m + t] = make_float2(lo, hi);
        }
    }
}

extern "C" void kernel_launch(void* const* d_in, const int* in_sizes, int n_in,
                              void* d_out, int out_size)
{
    const float* u   = (const float*)d_in[0];
    const int*   idx = (const int*)d_in[1];
    float*       out = (float*)d_out;
    fwht_kernel<<<NROWS, NT>>>(u, idx, out);
}